// round 15
// baseline (speedup 1.0000x reference)
#include <cuda_runtime.h>

// Problem constants (fixed by reference: B=2, S=4096, D=2)
#define S_DIM 4096

#define CT 1024        // attn: columns per block tile (256 threads * 4)
#define RT 32          // attn: rows per block tile
#define NT2 256

// Scratch (rule: no cudaMalloc — use __device__ globals).
// Fully overwritten each launch -> deterministic.
__device__ float g_thr[2];

// ---------------------------------------------------------------------------
// Pass 1 (O(S), replaces the 18us O(S^2) pairwise pass): closed-form moments.
//   sum_{i,j} d_ij  = 2S*Sa - 2(Sx^2+Sy^2)
//   sum_{i,j} d_ij^2= 2S*Saa + 2Sa^2 + 4(Sxx^2+2Sxy^2+Syy^2) - 8(Sax*Sx+Say*Sy)
// with a_i = x_i^2+y_i^2; i=j terms are exactly 0 so full-matrix sums are free.
// One block per batch; fixed-order double reduction (deterministic).
// ---------------------------------------------------------------------------
__global__ void __launch_bounds__(256)
moments_kernel(const float* __restrict__ r)
{
    __shared__ double red[8][8];   // [warp][moment]
    const int b = blockIdx.x;
    const float2* p = (const float2*)(r + (size_t)b * S_DIM * 2);

    // m = {Sx, Sy, Sxx, Syy, Sxy, Saa, Sax, Say}
    double m[8] = {0, 0, 0, 0, 0, 0, 0, 0};
    for (int i = threadIdx.x; i < S_DIM; i += 256) {
        const float2 q = p[i];
        const double x = q.x, y = q.y;
        const double x2 = x * x, y2 = y * y, a = x2 + y2;
        m[0] += x;      m[1] += y;
        m[2] += x2;     m[3] += y2;    m[4] += x * y;
        m[5] += a * a;  m[6] += a * x; m[7] += a * y;
    }

    #pragma unroll
    for (int o = 16; o > 0; o >>= 1)
        #pragma unroll
        for (int k = 0; k < 8; ++k)
            m[k] += __shfl_down_sync(0xffffffffu, m[k], o);

    const int w = threadIdx.x >> 5;
    if ((threadIdx.x & 31) == 0)
        #pragma unroll
        for (int k = 0; k < 8; ++k) red[w][k] = m[k];
    __syncthreads();

    if (threadIdx.x == 0) {
        double M[8];
        #pragma unroll
        for (int k = 0; k < 8; ++k) {
            double acc = red[0][k];
            #pragma unroll
            for (int ww = 1; ww < 8; ++ww) acc += red[ww][k];
            M[k] = acc;
        }
        const double Sx = M[0], Sy = M[1], Sxx = M[2], Syy = M[3], Sxy = M[4],
                     Saa = M[5], Sax = M[6], Say = M[7];
        const double Sn = (double)S_DIM;
        const double Sa = Sxx + Syy;
        const double sum_d = 2.0 * Sn * Sa - 2.0 * (Sx * Sx + Sy * Sy);
        const double sumsq = 2.0 * Sn * Saa + 2.0 * Sa * Sa
                           + 4.0 * (Sxx * Sxx + 2.0 * Sxy * Sxy + Syy * Syy)
                           - 8.0 * (Sax * Sx + Say * Sy);
        const double N = Sn * Sn;
        const double mean = sum_d / N;
        double var = (sumsq - sum_d * sum_d / N) / (N - 1.0);  // ddof=1
        if (var < 0.0) var = 0.0;
        g_thr[b] = (float)(mean + 1.25 * sqrt(var));
    }
}

// ---------------------------------------------------------------------------
// Pass 2: write the full [B,S,S] attention (unchanged from the passing R14
// kernel — it is already near the store roofline). Tile = RT rows x CT cols,
// each thread owns 4 consecutive columns (float4 store per row).
// bias = 0.5*(1+cos(atan2(dy,dx))) == 0.5 + 0.5*dx*rsqrt(dist_sq); 1.0 at d==0.
// Strictly-upper float4s take a pure zero-store fast path.
// ---------------------------------------------------------------------------
__global__ void __launch_bounds__(NT2)
attn_kernel(const float* __restrict__ r, float* __restrict__ out)
{
    __shared__ float2 srow[RT];

    const int b  = blockIdx.z;
    const int r0 = blockIdx.y * RT;
    const int j0 = blockIdx.x * CT + threadIdx.x * 4;
    const float thr = g_thr[b];

    const float2* coords = (const float2*)(r + (size_t)b * S_DIM * 2);
    if (threadIdx.x < RT) srow[threadIdx.x] = coords[r0 + threadIdx.x];
    __syncthreads();

    // 4 column coords, held in registers across all RT rows
    const float4* c4 = (const float4*)coords;
    const float4 ca = c4[j0 >> 1];
    const float4 cb = c4[(j0 >> 1) + 1];
    const float xj[4] = {ca.x, ca.z, cb.x, cb.z};
    const float yj[4] = {ca.y, ca.w, cb.y, cb.w};

    float* base = out + ((size_t)b * S_DIM + r0) * S_DIM + j0;

    #pragma unroll 1
    for (int k = 0; k < RT; ++k) {
        const int i = r0 + k;
        float4 o;
        if (j0 > i) {
            o = make_float4(0.f, 0.f, 0.f, 0.f);   // strictly above diagonal
        } else {
            const float2 pi = srow[k];
            float v[4];
            #pragma unroll
            for (int e = 0; e < 4; ++e) {
                const float dx = pi.x - xj[e];
                const float dy = pi.y - yj[e];
                const float d  = __fadd_rn(__fmul_rn(dx, dx), __fmul_rn(dy, dy));
                // d==0 -> atan2(0,1)=0 -> bias=1 (also covers diagonal)
                const float bias = (d == 0.f) ? 1.f
                                              : fmaf(0.5f * dx, rsqrtf(d), 0.5f);
                const bool ok = (d <= thr) && ((j0 + e) <= i);
                v[e] = ok ? bias : 0.f;
            }
            o = make_float4(v[0], v[1], v[2], v[3]);
        }
        *(float4*)(base + (size_t)k * S_DIM) = o;
    }
}

// ---------------------------------------------------------------------------
extern "C" void kernel_launch(void* const* d_in, const int* in_sizes, int n_in,
                              void* d_out, int out_size)
{
    const float* r = (const float*)d_in[0];
    float* out = (float*)d_out;
    const int B = in_sizes[0] / (S_DIM * 2);   // = 2

    moments_kernel<<<B, 256>>>(r);

    dim3 g2(S_DIM / CT, S_DIM / RT, B);        // (4, 128, B)
    attn_kernel<<<g2, NT2>>>(r, out);
}